// round 1
// baseline (speedup 1.0000x reference)
#include <cuda_runtime.h>
#include <math.h>

namespace {

constexpr int B_  = 4;
constexpr int TQ_ = 2048;
constexpr int TK_ = 2048;
constexpr int D_  = 1024;
constexpr int R_  = 64;
constexpr int H_  = 512;
constexpr int NF_ = D_ / 2 + 1;   // 513 rfft bins
constexpr int W2_ = 2 * NF_;      // 1026 (re | im)
constexpr int M_  = B_ * TQ_;     // 8192 total rows

// ---------------- scratch (__device__ globals; no runtime alloc allowed) ----
__device__ float g_CRI[D_ * W2_];      // forward DFT:  (D x 1026)  [cos | -sin]
__device__ float g_IMAT[W2_ * D_];     // inverse DFT:  (1026 x D)
__device__ float g_RoleN[R_ * D_];     // l2-normalized role rows
__device__ float g_RNspec[R_ * W2_];   // rfft of role rows
__device__ float g_Q[M_ * D_];
__device__ float g_K[M_ * D_];
__device__ float g_V[M_ * D_];
__device__ float g_KB[M_ * D_];        // K_bound (then normalized in place)
__device__ float g_H1[M_ * H_];
__device__ float g_Wt[M_ * R_];        // role logits -> softmax weights
__device__ float g_Fr[M_ * W2_];       // rfft(role_vecs)
__device__ float g_Ka[M_ * W2_];       // rfft(K)
__device__ float g_P[M_ * W2_];        // complex product
__device__ float g_S[B_ * TQ_ * TK_];  // raw scores (67 MB)
__device__ float g_CTX[M_ * D_];
__device__ float g_qnorm[M_];
__device__ float g_rs[M_];
__device__ float g_tau[B_];

// ---------------- DFT matrix fill -------------------------------------------
__global__ void fill_fwd_dft() {
    int idx = blockIdx.x * blockDim.x + threadIdx.x;
    if (idx >= D_ * W2_) return;
    int d = idx / W2_, f = idx % W2_;
    int fr = (f < NF_) ? f : (f - NF_);
    int m  = (int)(((long long)fr * d) % D_);
    float a = (float)m * (6.283185307179586f / (float)D_);
    g_CRI[idx] = (f < NF_) ? cosf(a) : -sinf(a);
}

__global__ void fill_inv_dft() {
    int idx = blockIdx.x * blockDim.x + threadIdx.x;
    if (idx >= W2_ * D_) return;
    int f = idx / D_, d = idx % D_;
    int fr = (f < NF_) ? f : (f - NF_);
    int m  = (int)(((long long)fr * d) % D_);
    float a = (float)m * (6.283185307179586f / (float)D_);
    float v;
    if (f < NF_) {
        float c = (fr == 0 || fr == D_ / 2) ? 1.0f : 2.0f;
        v = c * cosf(a) * (1.0f / (float)D_);
    } else {
        v = (fr == 0 || fr == D_ / 2) ? 0.0f : (-2.0f / (float)D_) * sinf(a);
    }
    g_IMAT[idx] = v;
}

// ---------------- row l2-normalize (optionally capture norms) ---------------
__global__ void rownorm_kernel(const float* __restrict__ in, float* __restrict__ out,
                               float* __restrict__ norms, int cols) {
    int row = blockIdx.x;
    const float* p = in + (size_t)row * cols;
    float s = 0.0f;
    for (int c = threadIdx.x; c < cols; c += blockDim.x) { float v = p[c]; s += v * v; }
    __shared__ float red[256];
    red[threadIdx.x] = s;
    __syncthreads();
    for (int o = 128; o > 0; o >>= 1) {
        if (threadIdx.x < o) red[threadIdx.x] += red[threadIdx.x + o];
        __syncthreads();
    }
    float nrm = sqrtf(red[0]);
    if (threadIdx.x == 0 && norms) norms[row] = nrm;
    float inv = 1.0f / fmaxf(nrm, 1e-12f);
    float* q = out + (size_t)row * cols;
    for (int c = threadIdx.x; c < cols; c += blockDim.x) q[c] = p[c] * inv;
}

// ---------------- astrocyte state + tau -------------------------------------
__global__ void astro_kernel(const float* __restrict__ qnorm,
                             const float* __restrict__ astro_in,
                             const float* __restrict__ astro_scale,
                             float* __restrict__ out_state) {
    int b = blockIdx.x;
    float s = 0.0f;
    for (int t = threadIdx.x; t < TQ_; t += blockDim.x) s += qnorm[b * TQ_ + t];
    __shared__ float red[256];
    red[threadIdx.x] = s;
    __syncthreads();
    for (int o = 128; o > 0; o >>= 1) {
        if (threadIdx.x < o) red[threadIdx.x] += red[threadIdx.x + o];
        __syncthreads();
    }
    if (threadIdx.x == 0) {
        float mean_surprise = red[0] / (32.0f * (float)TQ_);  // sqrt(D)=32
        float ns = 0.95f * astro_in[b] + 0.05f * mean_surprise;
        g_tau[b] = fmaxf(1.0f + astro_scale[0] * ns, 0.001f);
        out_state[b] = ns;
    }
}

// ---------------- softmax over R=64 (1 warp / row) --------------------------
__global__ void softmax64(float* __restrict__ x) {
    int warp = (blockIdx.x * blockDim.x + threadIdx.x) >> 5;
    int lane = threadIdx.x & 31;
    if (warp >= M_) return;
    float* p = x + (size_t)warp * R_;
    float v0 = p[lane], v1 = p[lane + 32];
    float m = fmaxf(v0, v1);
    #pragma unroll
    for (int o = 16; o > 0; o >>= 1) m = fmaxf(m, __shfl_xor_sync(0xffffffffu, m, o));
    float e0 = expf(v0 - m), e1 = expf(v1 - m);
    float sum = e0 + e1;
    #pragma unroll
    for (int o = 16; o > 0; o >>= 1) sum += __shfl_xor_sync(0xffffffffu, sum, o);
    float inv = 1.0f / sum;
    p[lane] = e0 * inv;
    p[lane + 32] = e1 * inv;
}

// ---------------- complex elementwise product -------------------------------
__global__ void cmul_kernel() {
    long long i = (long long)blockIdx.x * blockDim.x + threadIdx.x;
    if (i >= (long long)M_ * NF_) return;
    long long row = i / NF_;
    int f = (int)(i % NF_);
    const float* a = g_Ka + row * W2_;
    const float* b = g_Fr + row * W2_;
    float ar = a[f], ai = a[NF_ + f];
    float br = b[f], bi = b[NF_ + f];
    g_P[row * W2_ + f]       = ar * br - ai * bi;
    g_P[row * W2_ + NF_ + f] = ar * bi + ai * br;
}

// ---------------- score row-sum ---------------------------------------------
__global__ void rowsum_kernel(const float* __restrict__ S, float* __restrict__ rs) {
    int row = blockIdx.x;
    const float* p = S + (size_t)row * TK_;
    float s = 0.0f;
    for (int c = threadIdx.x; c < TK_; c += blockDim.x) s += p[c];
    __shared__ float red[256];
    red[threadIdx.x] = s;
    __syncthreads();
    for (int o = 128; o > 0; o >>= 1) {
        if (threadIdx.x < o) red[threadIdx.x] += red[threadIdx.x + o];
        __syncthreads();
    }
    if (threadIdx.x == 0) rs[row] = fmaxf(red[0], 1e-9f);
}

// ---------------- generic tiled SGEMM with fused epilogues ------------------
// EPI: 0=none, 1=+bias, 2=relu(+bias), 3=Epanechnikov score (bias=tau[z]),
//      4=divide by aux[z*M+row]
template <int EPI, bool TRB>
__global__ void __launch_bounds__(256, 2) gemm_k(
    const float* __restrict__ A, const float* __restrict__ B, float* __restrict__ C,
    int M, int N, int K,
    long long sA, long long sB, long long sC,
    const float* __restrict__ bias, const float* __restrict__ aux) {
    constexpr int BM = 128, BN = 128, BK = 16;
    __shared__ float As[BK][BM + 4];
    __shared__ float Bs[BK][BN + 4];

    int z = blockIdx.z;
    A += (long long)z * sA;
    B += (long long)z * sB;
    C += (long long)z * sC;

    int rowBase = blockIdx.y * BM;
    int colBase = blockIdx.x * BN;
    int tid = threadIdx.x;
    int tx = tid & 15;   // N dir
    int ty = tid >> 4;   // M dir

    float acc[8][8];
    #pragma unroll
    for (int i = 0; i < 8; i++)
        #pragma unroll
        for (int j = 0; j < 8; j++) acc[i][j] = 0.0f;

    for (int kt = 0; kt < K; kt += BK) {
        // A tile: BM x BK, stored transposed
        #pragma unroll
        for (int i = tid; i < BM * BK; i += 256) {
            int k = i & 15, m = i >> 4;
            int gm = rowBase + m, gk = kt + k;
            As[k][m] = (gm < M && gk < K) ? A[(long long)gm * K + gk] : 0.0f;
        }
        if (!TRB) {
            #pragma unroll
            for (int i = tid; i < BK * BN; i += 256) {
                int n = i & 127, k = i >> 7;
                int gk = kt + k, gn = colBase + n;
                Bs[k][n] = (gk < K && gn < N) ? B[(long long)gk * N + gn] : 0.0f;
            }
        } else {
            #pragma unroll
            for (int i = tid; i < BN * BK; i += 256) {
                int k = i & 15, n = i >> 4;
                int gn = colBase + n, gk = kt + k;
                Bs[k][n] = (gn < N && gk < K) ? B[(long long)gn * K + gk] : 0.0f;
            }
        }
        __syncthreads();
        #pragma unroll
        for (int k = 0; k < BK; k++) {
            float a[8], b[8];
            #pragma unroll
            for (int i = 0; i < 8; i++) a[i] = As[k][ty * 8 + i];
            #pragma unroll
            for (int j = 0; j < 8; j++) b[j] = Bs[k][tx * 8 + j];
            #pragma unroll
            for (int i = 0; i < 8; i++)
                #pragma unroll
                for (int j = 0; j < 8; j++) acc[i][j] += a[i] * b[j];
        }
        __syncthreads();
    }

    float tau = 0.0f;
    if (EPI == 3) tau = bias[z];

    #pragma unroll
    for (int i = 0; i < 8; i++) {
        int gm = rowBase + ty * 8 + i;
        if (gm >= M) continue;
        float rdiv = 1.0f;
        if (EPI == 4) rdiv = 1.0f / aux[(long long)z * M + gm];
        #pragma unroll
        for (int j = 0; j < 8; j++) {
            int gn = colBase + tx * 8 + j;
            if (gn >= N) continue;
            float v = acc[i][j];
            if (EPI == 1) v += bias[gn];
            else if (EPI == 2) v = fmaxf(v + bias[gn], 0.0f);
            else if (EPI == 3) {
                float x = (v + 1.0f) * 0.5f;
                float d = 1.0f - x;
                v = fmaxf(1.0f - tau * d * d, 0.0f);
            } else if (EPI == 4) v *= rdiv;
            C[(long long)gm * N + gn] = v;
        }
    }
}

static float* sym(const void* s) {
    void* p = nullptr;
    cudaGetSymbolAddress(&p, s);
    return (float*)p;
}

}  // namespace

extern "C" void kernel_launch(void* const* d_in, const int* in_sizes, int n_in,
                              void* d_out, int out_size) {
    const float* q_in  = (const float*)d_in[0];
    const float* k_in  = (const float*)d_in[1];
    const float* v_in  = (const float*)d_in[2];
    const float* astro = (const float*)d_in[3];
    const float* Wq = (const float*)d_in[4];
    const float* bq = (const float*)d_in[5];
    const float* Wk = (const float*)d_in[6];
    const float* bk = (const float*)d_in[7];
    const float* Wv = (const float*)d_in[8];
    const float* bv = (const float*)d_in[9];
    const float* Wo = (const float*)d_in[10];
    const float* bo = (const float*)d_in[11];
    const float* role_matrix = (const float*)d_in[12];
    const float* Wr1 = (const float*)d_in[13];
    const float* br1 = (const float*)d_in[14];
    const float* Wr2 = (const float*)d_in[15];
    const float* astro_scale = (const float*)d_in[16];
    float* out = (float*)d_out;

    float* CRI   = sym(g_CRI);
    float* IMAT  = sym(g_IMAT);
    float* RoleN = sym(g_RoleN);
    float* RNspec= sym(g_RNspec);
    float* Q     = sym(g_Q);
    float* Kp    = sym(g_K);
    float* Vp    = sym(g_V);
    float* KB    = sym(g_KB);
    float* H1    = sym(g_H1);
    float* Wt    = sym(g_Wt);
    float* Fr    = sym(g_Fr);
    float* Ka    = sym(g_Ka);
    float* P     = sym(g_P);
    float* S     = sym(g_S);
    float* CTX   = sym(g_CTX);
    float* qnorm = sym(g_qnorm);
    float* rs    = sym(g_rs);
    float* tau   = sym(g_tau);

    // 1. DFT matrices (cheap, recomputed every call — determinism requirement)
    fill_fwd_dft<<<(D_ * W2_ + 255) / 256, 256>>>();
    fill_inv_dft<<<(W2_ * D_ + 255) / 256, 256>>>();

    // 2. role rows normalize + their rfft spectra (tiny GEMM)
    rownorm_kernel<<<R_, 256>>>(role_matrix, RoleN, nullptr, D_);
    gemm_k<0, false><<<dim3((W2_ + 127) / 128, 1, 1), 256>>>(
        RoleN, CRI, RNspec, R_, W2_, D_, 0, 0, 0, nullptr, nullptr);

    // 3. Q, K, V projections
    gemm_k<1, false><<<dim3(8, 64, 1), 256>>>(q_in, Wq, Q,  M_, D_, D_, 0, 0, 0, bq, nullptr);
    gemm_k<1, false><<<dim3(8, 64, 1), 256>>>(k_in, Wk, Kp, M_, D_, D_, 0, 0, 0, bk, nullptr);
    gemm_k<1, false><<<dim3(8, 64, 1), 256>>>(v_in, Wv, Vp, M_, D_, D_, 0, 0, 0, bv, nullptr);

    // 4. Q norms (surprise) + normalize Q in place; astro state / tau
    rownorm_kernel<<<M_, 256>>>(Q, Q, qnorm, D_);
    astro_kernel<<<B_, 256>>>(qnorm, astro, astro_scale, out + (out_size - B_));

    // 5. role MLP -> softmax weights
    gemm_k<2, false><<<dim3(4, 64, 1), 256>>>(Kp, Wr1, H1, M_, H_, D_, 0, 0, 0, br1, nullptr);
    gemm_k<0, false><<<dim3(1, 64, 1), 256>>>(H1, Wr2, Wt, M_, R_, H_, 0, 0, 0, nullptr, nullptr);
    softmax64<<<M_ / 8, 256>>>(Wt);

    // 6. holographic binding in frequency domain (all GEMMs)
    gemm_k<0, false><<<dim3((W2_ + 127) / 128, 64, 1), 256>>>(
        Wt, RNspec, Fr, M_, W2_, R_, 0, 0, 0, nullptr, nullptr);
    gemm_k<0, false><<<dim3((W2_ + 127) / 128, 64, 1), 256>>>(
        Kp, CRI, Ka, M_, W2_, D_, 0, 0, 0, nullptr, nullptr);
    cmul_kernel<<<(int)(((long long)M_ * NF_ + 255) / 256), 256>>>();
    gemm_k<0, false><<<dim3(8, 64, 1), 256>>>(P, IMAT, KB, M_, D_, W2_, 0, 0, 0, nullptr, nullptr);

    // 7. normalize K_bound in place
    rownorm_kernel<<<M_, 256>>>(KB, KB, nullptr, D_);

    // 8. scores: Epanechnikov kernel on cosine sim (batched, B transposed)
    gemm_k<3, true><<<dim3(16, 16, B_), 256>>>(
        Q, KB, S, TQ_, TK_, D_,
        (long long)TQ_ * D_, (long long)TK_ * D_, (long long)TQ_ * TK_, tau, nullptr);

    // 9. normalization denominator, then context = (S @ V) / rowsum
    rowsum_kernel<<<M_, 256>>>(S, rs);
    gemm_k<4, false><<<dim3(8, 16, B_), 256>>>(
        S, Vp, CTX, TQ_, D_, TK_,
        (long long)TQ_ * TK_, (long long)TK_ * D_, (long long)TQ_ * D_, nullptr, rs);

    // 10. output projection straight into d_out
    gemm_k<1, false><<<dim3(8, 64, 1), 256>>>(CTX, Wo, out, M_, D_, D_, 0, 0, 0, bo, nullptr);
}

// round 3
// speedup vs baseline: 2.3438x; 2.3438x over previous
#include <cuda_runtime.h>
#include <math.h>

namespace {

constexpr int B_   = 4;
constexpr int TQ_  = 2048;
constexpr int TK_  = 2048;
constexpr int D_   = 1024;
constexpr int R_   = 64;
constexpr int H_   = 512;
constexpr int NF_  = D_ / 2 + 1;   // 513 rfft bins
constexpr int W2_  = 2 * NF_;      // 1026 (re | im)
constexpr int W2P_ = 1040;         // padded to multiple of 16
constexpr int M_   = B_ * TQ_;     // 8192 rows

// ---------------- scratch ----------------------------------------------------
__device__ __align__(128) float g_CRI[D_ * W2P_];
__device__ __align__(128) float g_IMAT[W2P_ * D_];
__device__ __align__(128) float g_RoleN[R_ * D_];
__device__ __align__(128) float g_RNspec[R_ * W2P_];
__device__ __align__(128) float g_Q[M_ * D_];
__device__ __align__(128) float g_K[M_ * D_];
__device__ __align__(128) float g_V[M_ * D_];
__device__ __align__(128) float g_KB[M_ * D_];
__device__ __align__(128) float g_H1[M_ * H_];
__device__ __align__(128) float g_Wt[M_ * R_];
__device__ __align__(128) float g_Fr[M_ * W2P_];
__device__ __align__(128) float g_Ka[M_ * W2P_];
__device__ __align__(128) float g_P[M_ * W2P_];   // pad cols never written -> stay 0
__device__ __align__(128) float g_S[B_ * TQ_ * TK_];
__device__ __align__(128) float g_CTX[M_ * D_];
__device__ __align__(128) float g_qnorm[M_];
__device__ __align__(128) float g_rs[M_];
__device__ __align__(128) float g_tau[B_];

// ---------------- DFT matrix fill --------------------------------------------
__global__ void fill_fwd_dft() {
    int idx = blockIdx.x * blockDim.x + threadIdx.x;
    if (idx >= D_ * W2P_) return;
    int d = idx / W2P_, f = idx % W2P_;
    float v = 0.0f;
    if (f < W2_) {
        int fr = (f < NF_) ? f : (f - NF_);
        int m  = (int)(((long long)fr * d) % D_);
        float a = (float)m * (6.283185307179586f / (float)D_);
        v = (f < NF_) ? cosf(a) : -sinf(a);
    }
    g_CRI[idx] = v;
}

__global__ void fill_inv_dft() {
    int idx = blockIdx.x * blockDim.x + threadIdx.x;
    if (idx >= W2P_ * D_) return;
    int f = idx / D_, d = idx % D_;
    float v = 0.0f;
    if (f < W2_) {
        int fr = (f < NF_) ? f : (f - NF_);
        int m  = (int)(((long long)fr * d) % D_);
        float a = (float)m * (6.283185307179586f / (float)D_);
        if (f < NF_) {
            float c = (fr == 0 || fr == D_ / 2) ? 1.0f : 2.0f;
            v = c * cosf(a) * (1.0f / (float)D_);
        } else {
            v = (fr == 0 || fr == D_ / 2) ? 0.0f : (-2.0f / (float)D_) * sinf(a);
        }
    }
    g_IMAT[idx] = v;
}

// ---------------- row l2-normalize -------------------------------------------
__global__ void rownorm_kernel(const float* __restrict__ in, float* __restrict__ out,
                               float* __restrict__ norms, int cols) {
    int row = blockIdx.x;
    const float* p = in + (size_t)row * cols;
    float s = 0.0f;
    for (int c = threadIdx.x; c < cols; c += blockDim.x) { float v = p[c]; s += v * v; }
    __shared__ float red[256];
    red[threadIdx.x] = s;
    __syncthreads();
    for (int o = 128; o > 0; o >>= 1) {
        if (threadIdx.x < o) red[threadIdx.x] += red[threadIdx.x + o];
        __syncthreads();
    }
    float nrm = sqrtf(red[0]);
    if (threadIdx.x == 0 && norms) norms[row] = nrm;
    float inv = 1.0f / fmaxf(nrm, 1e-12f);
    float* q = out + (size_t)row * cols;
    for (int c = threadIdx.x; c < cols; c += blockDim.x) q[c] = p[c] * inv;
}

// ---------------- astrocyte state + tau --------------------------------------
__global__ void astro_kernel(const float* __restrict__ qnorm,
                             const float* __restrict__ astro_in,
                             const float* __restrict__ astro_scale,
                             float* __restrict__ out_state) {
    int b = blockIdx.x;
    float s = 0.0f;
    for (int t = threadIdx.x; t < TQ_; t += blockDim.x) s += qnorm[b * TQ_ + t];
    __shared__ float red[256];
    red[threadIdx.x] = s;
    __syncthreads();
    for (int o = 128; o > 0; o >>= 1) {
        if (threadIdx.x < o) red[threadIdx.x] += red[threadIdx.x + o];
        __syncthreads();
    }
    if (threadIdx.x == 0) {
        float mean_surprise = red[0] / (32.0f * (float)TQ_);
        float ns = 0.95f * astro_in[b] + 0.05f * mean_surprise;
        g_tau[b] = fmaxf(1.0f + astro_scale[0] * ns, 0.001f);
        out_state[b] = ns;
    }
}

// ---------------- softmax over R=64 ------------------------------------------
__global__ void softmax64(float* __restrict__ x) {
    int warp = (blockIdx.x * blockDim.x + threadIdx.x) >> 5;
    int lane = threadIdx.x & 31;
    if (warp >= M_) return;
    float* p = x + (size_t)warp * R_;
    float v0 = p[lane], v1 = p[lane + 32];
    float m = fmaxf(v0, v1);
    #pragma unroll
    for (int o = 16; o > 0; o >>= 1) m = fmaxf(m, __shfl_xor_sync(0xffffffffu, m, o));
    float e0 = expf(v0 - m), e1 = expf(v1 - m);
    float sum = e0 + e1;
    #pragma unroll
    for (int o = 16; o > 0; o >>= 1) sum += __shfl_xor_sync(0xffffffffu, sum, o);
    float inv = 1.0f / sum;
    p[lane] = e0 * inv;
    p[lane + 32] = e1 * inv;
}

// ---------------- complex elementwise product --------------------------------
__global__ void cmul_kernel() {
    long long i = (long long)blockIdx.x * blockDim.x + threadIdx.x;
    if (i >= (long long)M_ * NF_) return;
    long long row = i / NF_;
    int f = (int)(i % NF_);
    const float* a = g_Ka + row * W2P_;
    const float* b = g_Fr + row * W2P_;
    float ar = a[f], ai = a[NF_ + f];
    float br = b[f], bi = b[NF_ + f];
    g_P[row * W2P_ + f]       = ar * br - ai * bi;
    g_P[row * W2P_ + NF_ + f] = ar * bi + ai * br;
}

// ---------------- score row-sum ----------------------------------------------
__global__ void rowsum_kernel(const float* __restrict__ S, float* __restrict__ rs) {
    int row = blockIdx.x;
    const float* p = S + (size_t)row * TK_;
    float s = 0.0f;
    for (int c = threadIdx.x; c < TK_; c += blockDim.x) s += p[c];
    __shared__ float red[256];
    red[threadIdx.x] = s;
    __syncthreads();
    for (int o = 128; o > 0; o >>= 1) {
        if (threadIdx.x < o) red[threadIdx.x] += red[threadIdx.x + o];
        __syncthreads();
    }
    if (threadIdx.x == 0) rs[row] = fmaxf(red[0], 1e-9f);
}

// ---------------- tf32 helpers -----------------------------------------------
__device__ __forceinline__ unsigned tf32u(float x) {
    unsigned u;
    asm("cvt.rna.tf32.f32 %0, %1;" : "=r"(u) : "f"(x));
    return u;
}

__device__ __forceinline__ void mma8(float* c, const unsigned* a, unsigned b0, unsigned b1) {
    asm volatile(
        "mma.sync.aligned.m16n8k8.row.col.f32.tf32.tf32.f32 "
        "{%0,%1,%2,%3},{%4,%5,%6,%7},{%8,%9},{%0,%1,%2,%3};"
        : "+f"(c[0]), "+f"(c[1]), "+f"(c[2]), "+f"(c[3])
        : "r"(a[0]), "r"(a[1]), "r"(a[2]), "r"(a[3]), "r"(b0), "r"(b1));
}

// ---------------- tf32 tensor-core GEMM --------------------------------------
// EPI: 0=none, 1=+bias, 2=relu(+bias), 3=Epanechnikov (bias=tau[z]), 4=/aux[z*M+row]
// PASSES: 1 = single tf32, 3 = tf32x3 (fp32-class accuracy)
template <int EPI, bool TRB, int PASSES>
__global__ void __launch_bounds__(256) mma_gemm(
    const float* __restrict__ Ag, const float* __restrict__ Bg, float* __restrict__ Cg,
    int M, int N, int K, long long sA, long long sB, long long sC,
    const float* __restrict__ bias, const float* __restrict__ aux) {
    constexpr int BM = 128, BN = 128, BK = 16;
    constexpr int APAD = BK + 4;    // 20 -> conflict-free A fragment LDS
    constexpr int BPAD = BN + 8;    // 136 -> conflict-free B fragment LDS
    constexpr int NBUF = (PASSES == 3) ? 2 : 1;
    __shared__ float As[NBUF][BM * APAD];
    __shared__ float Bs[NBUF][BK * BPAD];

    const int z = blockIdx.z;
    const float* A = Ag + (long long)z * sA;
    const float* B = Bg + (long long)z * sB;
    float* C = Cg + (long long)z * sC;

    const int rowBase = blockIdx.y * BM;
    const int colBase = blockIdx.x * BN;
    const int tid = threadIdx.x;
    const int lane = tid & 31, warp = tid >> 5;
    const int wm = warp >> 1, wn = warp & 1;  // 4 x 2 warp grid
    const int lrow = lane >> 2, lcol = lane & 3;

    const bool fullTile = (rowBase + BM <= M) && (colBase + BN <= N);

    float acc[2][8][4];
    #pragma unroll
    for (int i = 0; i < 2; i++)
        #pragma unroll
        for (int j = 0; j < 8; j++)
            #pragma unroll
            for (int e = 0; e < 4; e++) acc[i][j][e] = 0.0f;

    const int am = tid >> 2, ak = (tid & 3) * 4;   // A stage
    const int bk = tid >> 4, bn = (tid & 15) * 4;  // B stage (K-major)
    const int tn = tid >> 2, tk = (tid & 3) * 4;   // B stage (transposed)

    float4 stA[2], stB[2];
    const float4 zero4 = make_float4(0.f, 0.f, 0.f, 0.f);

    auto ldA = [&](int kt) {
        #pragma unroll
        for (int h = 0; h < 2; h++) {
            int gm = rowBase + am + h * 64;
            stA[h] = (gm < M) ? *reinterpret_cast<const float4*>(A + (long long)gm * K + kt + ak)
                              : zero4;
        }
    };
    auto ldB = [&](int kt) {
        if (!TRB) {
            #pragma unroll
            for (int h = 0; h < 2; h++) {
                int gn = colBase + bn + h * 64;
                stB[h] = (gn < N) ? *reinterpret_cast<const float4*>(B + (long long)(kt + bk) * N + gn)
                                  : zero4;
            }
        } else {
            #pragma unroll
            for (int h = 0; h < 2; h++) {
                int gn = colBase + tn + h * 64;
                stB[h] = (gn < N) ? *reinterpret_cast<const float4*>(B + (long long)gn * K + kt + tk)
                                  : zero4;
            }
        }
    };
    auto stage = [&]() {
        #pragma unroll
        for (int h = 0; h < 2; h++) {
            int base = (am + h * 64) * APAD + ak;
            if constexpr (PASSES == 3) {
                float4 v = stA[h];
                float4 hi = make_float4(__uint_as_float(tf32u(v.x)), __uint_as_float(tf32u(v.y)),
                                        __uint_as_float(tf32u(v.z)), __uint_as_float(tf32u(v.w)));
                *reinterpret_cast<float4*>(&As[0][base]) = hi;
                *reinterpret_cast<float4*>(&As[1][base]) =
                    make_float4(v.x - hi.x, v.y - hi.y, v.z - hi.z, v.w - hi.w);
            } else {
                *reinterpret_cast<float4*>(&As[0][base]) = stA[h];
            }
        }
        if (!TRB) {
            #pragma unroll
            for (int h = 0; h < 2; h++) {
                int base = bk * BPAD + bn + h * 64;
                if constexpr (PASSES == 3) {
                    float4 v = stB[h];
                    float4 hi = make_float4(__uint_as_float(tf32u(v.x)), __uint_as_float(tf32u(v.y)),
                                            __uint_as_float(tf32u(v.z)), __uint_as_float(tf32u(v.w)));
                    *reinterpret_cast<float4*>(&Bs[0][base]) = hi;
                    *reinterpret_cast<float4*>(&Bs[1][base]) =
                        make_float4(v.x - hi.x, v.y - hi.y, v.z - hi.z, v.w - hi.w);
                } else {
                    *reinterpret_cast<float4*>(&Bs[0][base]) = stB[h];
                }
            }
        } else {
            #pragma unroll
            for (int h = 0; h < 2; h++) {
                int col = tn + h * 64;
                float v[4] = {stB[h].x, stB[h].y, stB[h].z, stB[h].w};
                #pragma unroll
                for (int j = 0; j < 4; j++) {
                    if constexpr (PASSES == 3) {
                        float hi = __uint_as_float(tf32u(v[j]));
                        Bs[0][(tk + j) * BPAD + col] = hi;
                        Bs[1][(tk + j) * BPAD + col] = v[j] - hi;
                    } else {
                        Bs[0][(tk + j) * BPAD + col] = v[j];
                    }
                }
            }
        }
    };

    ldA(0); ldB(0);
    for (int kt = 0; kt < K; kt += BK) {
        __syncthreads();
        stage();
        __syncthreads();
        if (kt + BK < K) { ldA(kt + BK); ldB(kt + BK); }
        #pragma unroll
        for (int ks = 0; ks < 2; ks++) {
            const int k0 = ks * 8;
            unsigned ah[2][4], al[2][4];
            #pragma unroll
            for (int mt = 0; mt < 2; mt++) {
                int mb = (wm * 32 + mt * 16 + lrow) * APAD + k0 + lcol;
                ah[mt][0] = __float_as_uint(As[0][mb]);
                ah[mt][1] = __float_as_uint(As[0][mb + 8 * APAD]);
                ah[mt][2] = __float_as_uint(As[0][mb + 4]);
                ah[mt][3] = __float_as_uint(As[0][mb + 8 * APAD + 4]);
                if constexpr (PASSES == 3) {
                    al[mt][0] = __float_as_uint(As[1][mb]);
                    al[mt][1] = __float_as_uint(As[1][mb + 8 * APAD]);
                    al[mt][2] = __float_as_uint(As[1][mb + 4]);
                    al[mt][3] = __float_as_uint(As[1][mb + 8 * APAD + 4]);
                }
            }
            #pragma unroll
            for (int nt = 0; nt < 8; nt++) {
                int nb = (k0 + lcol) * BPAD + wn * 64 + nt * 8 + lrow;
                unsigned bh0 = __float_as_uint(Bs[0][nb]);
                unsigned bh1 = __float_as_uint(Bs[0][nb + 4 * BPAD]);
                #pragma unroll
                for (int mt = 0; mt < 2; mt++) mma8(acc[mt][nt], ah[mt], bh0, bh1);
                if constexpr (PASSES == 3) {
                    unsigned bl0 = __float_as_uint(Bs[1][nb]);
                    unsigned bl1 = __float_as_uint(Bs[1][nb + 4 * BPAD]);
                    #pragma unroll
                    for (int mt = 0; mt < 2; mt++) {
                        mma8(acc[mt][nt], al[mt], bh0, bh1);
                        mma8(acc[mt][nt], ah[mt], bl0, bl1);
                    }
                }
            }
        }
    }

    float tau = (EPI == 3) ? bias[z] : 0.0f;
    #pragma unroll
    for (int mt = 0; mt < 2; mt++) {
        int gm0 = rowBase + wm * 32 + mt * 16 + lrow;
        int gm1 = gm0 + 8;
        float rd0 = 1.0f, rd1 = 1.0f;
        if (EPI == 4) {
            if (fullTile || gm0 < M) rd0 = 1.0f / aux[(long long)z * M + gm0];
            if (fullTile || gm1 < M) rd1 = 1.0f / aux[(long long)z * M + gm1];
        }
        #pragma unroll
        for (int nt = 0; nt < 8; nt++) {
            int gc = colBase + wn * 64 + nt * 8 + lcol * 2;
            #pragma unroll
            for (int e = 0; e < 4; e++) {
                int gm = (e < 2) ? gm0 : gm1;
                int gn = gc + (e & 1);
                if (!fullTile && (gm >= M || gn >= N)) continue;
                float v = acc[mt][nt][e];
                if (EPI == 1) v += bias[gn];
                else if (EPI == 2) v = fmaxf(v + bias[gn], 0.0f);
                else if (EPI == 3) {
                    float x = (v + 1.0f) * 0.5f;
                    float d = 1.0f - x;
                    v = fmaxf(1.0f - tau * d * d, 0.0f);
                } else if (EPI == 4) v *= (e < 2) ? rd0 : rd1;
                C[(long long)gm * N + gn] = v;
            }
        }
    }
}

static float* sym(const void* s) {
    void* p = nullptr;
    cudaGetSymbolAddress(&p, s);
    return (float*)p;
}

}  // namespace

extern "C" void kernel_launch(void* const* d_in, const int* in_sizes, int n_in,
                              void* d_out, int out_size) {
    const float* q_in  = (const float*)d_in[0];
    const float* k_in  = (const float*)d_in[1];
    const float* v_in  = (const float*)d_in[2];
    const float* astro = (const float*)d_in[3];
    const float* Wq = (const float*)d_in[4];
    const float* bq = (const float*)d_in[5];
    const float* Wk = (const float*)d_in[6];
    const float* bk = (const float*)d_in[7];
    const float* Wv = (const float*)d_in[8];
    const float* bv = (const float*)d_in[9];
    const float* Wo = (const float*)d_in[10];
    const float* bo = (const float*)d_in[11];
    const float* role_matrix = (const float*)d_in[12];
    const float* Wr1 = (const float*)d_in[13];
    const float* br1 = (const float*)d_in[14];
    const float* Wr2 = (const float*)d_in[15];
    const float* astro_scale = (const float*)d_in[16];
    float* out = (float*)d_out;

    float* CRI    = sym(g_CRI);
    float* IMAT   = sym(g_IMAT);
    float* RoleN  = sym(g_RoleN);
    float* RNspec = sym(g_RNspec);
    float* Q      = sym(g_Q);
    float* Kp     = sym(g_K);
    float* Vp     = sym(g_V);
    float* KB     = sym(g_KB);
    float* H1     = sym(g_H1);
    float* Wt     = sym(g_Wt);
    float* Fr     = sym(g_Fr);
    float* Ka     = sym(g_Ka);
    float* P      = sym(g_P);
    float* S      = sym(g_S);
    float* CTX    = sym(g_CTX);
    float* qnorm  = sym(g_qnorm);
    float* rs     = sym(g_rs);
    float* tau    = sym(g_tau);

    // 1. DFT matrices
    fill_fwd_dft<<<(D_ * W2P_ + 255) / 256, 256>>>();
    fill_inv_dft<<<(W2P_ * D_ + 255) / 256, 256>>>();

    // 2. role rows normalize + spectra
    rownorm_kernel<<<R_, 256>>>(role_matrix, RoleN, nullptr, D_);
    mma_gemm<0, false, 1><<<dim3(9, 1, 1), 256>>>(
        RoleN, CRI, RNspec, R_, W2P_, D_, 0, 0, 0, nullptr, nullptr);

    // 3. Q, K, V projections (V is on the value path -> tf32x3)
    mma_gemm<1, false, 1><<<dim3(8, 64, 1), 256>>>(q_in, Wq, Q,  M_, D_, D_, 0, 0, 0, bq, nullptr);
    mma_gemm<1, false, 1><<<dim3(8, 64, 1), 256>>>(k_in, Wk, Kp, M_, D_, D_, 0, 0, 0, bk, nullptr);
    mma_gemm<1, false, 3><<<dim3(8, 64, 1), 256>>>(v_in, Wv, Vp, M_, D_, D_, 0, 0, 0, bv, nullptr);

    // 4. surprise + astro state
    rownorm_kernel<<<M_, 256>>>(Q, Q, qnorm, D_);
    astro_kernel<<<B_, 256>>>(qnorm, astro, astro_scale, out + (out_size - B_));

    // 5. role MLP -> softmax weights
    mma_gemm<2, false, 1><<<dim3(4, 64, 1), 256>>>(Kp, Wr1, H1, M_, H_, D_, 0, 0, 0, br1, nullptr);
    mma_gemm<0, false, 1><<<dim3(1, 64, 1), 256>>>(H1, Wr2, Wt, M_, R_, H_, 0, 0, 0, nullptr, nullptr);
    softmax64<<<M_ / 8, 256>>>(Wt);

    // 6. holographic binding in frequency domain
    mma_gemm<0, false, 1><<<dim3(9, 64, 1), 256>>>(
        Wt, RNspec, Fr, M_, W2P_, R_, 0, 0, 0, nullptr, nullptr);
    mma_gemm<0, false, 1><<<dim3(9, 64, 1), 256>>>(
        Kp, CRI, Ka, M_, W2P_, D_, 0, 0, 0, nullptr, nullptr);
    cmul_kernel<<<(int)(((long long)M_ * NF_ + 255) / 256), 256>>>();
    mma_gemm<0, false, 1><<<dim3(8, 64, 1), 256>>>(
        P, IMAT, KB, M_, D_, W2P_, 0, 0, 0, nullptr, nullptr);

    // 7. normalize K_bound
    rownorm_kernel<<<M_, 256>>>(KB, KB, nullptr, D_);

    // 8. Epanechnikov scores on cosine sim
    mma_gemm<3, true, 1><<<dim3(16, 16, B_), 256>>>(
        Q, KB, S, TQ_, TK_, D_,
        (long long)TQ_ * D_, (long long)TK_ * D_, (long long)TQ_ * TK_, tau, nullptr);

    // 9. denominators, then context = (S @ V) / rowsum   (value path -> tf32x3)
    rowsum_kernel<<<M_, 256>>>(S, rs);
    mma_gemm<4, false, 3><<<dim3(8, 16, B_), 256>>>(
        S, Vp, CTX, TQ_, D_, TK_,
        (long long)TQ_ * TK_, (long long)TK_ * D_, (long long)TQ_ * D_, nullptr, rs);

    // 10. output projection (value path -> tf32x3)
    mma_gemm<1, false, 3><<<dim3(8, 64, 1), 256>>>(CTX, Wo, out, M_, D_, D_, 0, 0, 0, bo, nullptr);
}

// round 6
// speedup vs baseline: 2.3446x; 1.0003x over previous
#include <cuda_runtime.h>
#include <math.h>

namespace {

constexpr int B_   = 4;
constexpr int TQ_  = 2048;
constexpr int TK_  = 2048;
constexpr int D_   = 1024;
constexpr int R_   = 64;
constexpr int H_   = 512;
constexpr int NF_  = D_ / 2 + 1;   // 513 rfft bins
constexpr int W2_  = 2 * NF_;      // 1026 (re | im)
constexpr int W2P_ = 1040;         // padded to multiple of 16
constexpr int M_   = B_ * TQ_;     // 8192 rows

// ---------------- scratch ----------------------------------------------------
__device__ __align__(128) float g_CRI[D_ * W2P_];
__device__ __align__(128) float g_IMAT[W2P_ * D_];
__device__ __align__(128) float g_RoleN[R_ * D_];
__device__ __align__(128) float g_RNspec[R_ * W2P_];
__device__ __align__(128) float g_Q[M_ * D_];
__device__ __align__(128) float g_K[M_ * D_];
__device__ __align__(128) float g_V[M_ * D_];
__device__ __align__(128) float g_KB[M_ * D_];
__device__ __align__(128) float g_H1[M_ * H_];
__device__ __align__(128) float g_Wt[M_ * R_];
__device__ __align__(128) float g_Fr[M_ * W2P_];
__device__ __align__(128) float g_Ka[M_ * W2P_];
__device__ __align__(128) float g_P[M_ * W2P_];   // pad cols never written -> stay 0
__device__ __align__(128) float g_S[B_ * TQ_ * TK_];
__device__ __align__(128) float g_CTX[M_ * D_];
__device__ __align__(128) float g_qnorm[M_];
__device__ __align__(128) float g_rs[M_];
__device__ __align__(128) float g_tau[B_];

// ---------------- DFT matrix fill --------------------------------------------
__global__ void fill_fwd_dft() {
    int idx = blockIdx.x * blockDim.x + threadIdx.x;
    if (idx >= D_ * W2P_) return;
    int d = idx / W2P_, f = idx % W2P_;
    float v = 0.0f;
    if (f < W2_) {
        int fr = (f < NF_) ? f : (f - NF_);
        int m  = (int)(((long long)fr * d) % D_);
        float a = (float)m * (6.283185307179586f / (float)D_);
        v = (f < NF_) ? cosf(a) : -sinf(a);
    }
    g_CRI[idx] = v;
}

__global__ void fill_inv_dft() {
    int idx = blockIdx.x * blockDim.x + threadIdx.x;
    if (idx >= W2P_ * D_) return;
    int f = idx / D_, d = idx % D_;
    float v = 0.0f;
    if (f < W2_) {
        int fr = (f < NF_) ? f : (f - NF_);
        int m  = (int)(((long long)fr * d) % D_);
        float a = (float)m * (6.283185307179586f / (float)D_);
        if (f < NF_) {
            float c = (fr == 0 || fr == D_ / 2) ? 1.0f : 2.0f;
            v = c * cosf(a) * (1.0f / (float)D_);
        } else {
            v = (fr == 0 || fr == D_ / 2) ? 0.0f : (-2.0f / (float)D_) * sinf(a);
        }
    }
    g_IMAT[idx] = v;
}

// ---------------- row l2-normalize -------------------------------------------
__global__ void rownorm_kernel(const float* __restrict__ in, float* __restrict__ out,
                               float* __restrict__ norms, int cols) {
    int row = blockIdx.x;
    const float* p = in + (size_t)row * cols;
    float s = 0.0f;
    for (int c = threadIdx.x; c < cols; c += blockDim.x) { float v = p[c]; s += v * v; }
    __shared__ float red[256];
    red[threadIdx.x] = s;
    __syncthreads();
    for (int o = 128; o > 0; o >>= 1) {
        if (threadIdx.x < o) red[threadIdx.x] += red[threadIdx.x + o];
        __syncthreads();
    }
    float nrm = sqrtf(red[0]);
    if (threadIdx.x == 0 && norms) norms[row] = nrm;
    float inv = 1.0f / fmaxf(nrm, 1e-12f);
    float* q = out + (size_t)row * cols;
    for (int c = threadIdx.x; c < cols; c += blockDim.x) q[c] = p[c] * inv;
}

// ---------------- astrocyte state + tau --------------------------------------
__global__ void astro_kernel(const float* __restrict__ qnorm,
                             const float* __restrict__ astro_in,
                             const float* __restrict__ astro_scale,
                             float* __restrict__ out_state) {
    int b = blockIdx.x;
    float s = 0.0f;
    for (int t = threadIdx.x; t < TQ_; t += blockDim.x) s += qnorm[b * TQ_ + t];
    __shared__ float red[256];
    red[threadIdx.x] = s;
    __syncthreads();
    for (int o = 128; o > 0; o >>= 1) {
        if (threadIdx.x < o) red[threadIdx.x] += red[threadIdx.x + o];
        __syncthreads();
    }
    if (threadIdx.x == 0) {
        float mean_surprise = red[0] / (32.0f * (float)TQ_);
        float ns = 0.95f * astro_in[b] + 0.05f * mean_surprise;
        g_tau[b] = fmaxf(1.0f + astro_scale[0] * ns, 0.001f);
        out_state[b] = ns;
    }
}

// ---------------- softmax over R=64 ------------------------------------------
__global__ void softmax64(float* __restrict__ x) {
    int warp = (blockIdx.x * blockDim.x + threadIdx.x) >> 5;
    int lane = threadIdx.x & 31;
    if (warp >= M_) return;
    float* p = x + (size_t)warp * R_;
    float v0 = p[lane], v1 = p[lane + 32];
    float m = fmaxf(v0, v1);
    #pragma unroll
    for (int o = 16; o > 0; o >>= 1) m = fmaxf(m, __shfl_xor_sync(0xffffffffu, m, o));
    float e0 = expf(v0 - m), e1 = expf(v1 - m);
    float sum = e0 + e1;
    #pragma unroll
    for (int o = 16; o > 0; o >>= 1) sum += __shfl_xor_sync(0xffffffffu, sum, o);
    float inv = 1.0f / sum;
    p[lane] = e0 * inv;
    p[lane + 32] = e1 * inv;
}

// ---------------- complex elementwise product --------------------------------
__global__ void cmul_kernel() {
    long long i = (long long)blockIdx.x * blockDim.x + threadIdx.x;
    if (i >= (long long)M_ * NF_) return;
    long long row = i / NF_;
    int f = (int)(i % NF_);
    const float* a = g_Ka + row * W2P_;
    const float* b = g_Fr + row * W2P_;
    float ar = a[f], ai = a[NF_ + f];
    float br = b[f], bi = b[NF_ + f];
    g_P[row * W2P_ + f]       = ar * br - ai * bi;
    g_P[row * W2P_ + NF_ + f] = ar * bi + ai * br;
}

// ---------------- score row-sum ----------------------------------------------
__global__ void rowsum_kernel(const float* __restrict__ S, float* __restrict__ rs) {
    int row = blockIdx.x;
    const float* p = S + (size_t)row * TK_;
    float s = 0.0f;
    for (int c = threadIdx.x; c < TK_; c += blockDim.x) s += p[c];
    __shared__ float red[256];
    red[threadIdx.x] = s;
    __syncthreads();
    for (int o = 128; o > 0; o >>= 1) {
        if (threadIdx.x < o) red[threadIdx.x] += red[threadIdx.x + o];
        __syncthreads();
    }
    if (threadIdx.x == 0) rs[row] = fmaxf(red[0], 1e-9f);
}

// ---------------- tf32 helpers -----------------------------------------------
__device__ __forceinline__ unsigned tf32u(float x) {
    unsigned u;
    asm("cvt.rna.tf32.f32 %0, %1;" : "=r"(u) : "f"(x));
    return u;
}

__device__ __forceinline__ void mma8(float* c, const unsigned* a, unsigned b0, unsigned b1) {
    asm volatile(
        "mma.sync.aligned.m16n8k8.row.col.f32.tf32.tf32.f32 "
        "{%0,%1,%2,%3},{%4,%5,%6,%7},{%8,%9},{%0,%1,%2,%3};"
        : "+f"(c[0]), "+f"(c[1]), "+f"(c[2]), "+f"(c[3])
        : "r"(a[0]), "r"(a[1]), "r"(a[2]), "r"(a[3]), "r"(b0), "r"(b1));
}

// ---------------- tf32 tensor-core GEMM --------------------------------------
// EPI: 0=none, 1=+bias, 2=relu(+bias), 3=Epanechnikov (bias=tau[z]), 4=/aux[z*M+row]
// PASSES: 1 = single tf32, 3 = tf32x3 (fp32-class accuracy)
template <int EPI, bool TRB, int PASSES>
__global__ void __launch_bounds__(256) mma_gemm(
    const float* __restrict__ Ag, const float* __restrict__ Bg, float* __restrict__ Cg,
    int M, int N, int K, long long sA, long long sB, long long sC,
    const float* __restrict__ bias, const float* __restrict__ aux) {
    constexpr int BM = 128, BN = 128, BK = 16;
    constexpr int APAD = BK + 4;    // 20 -> conflict-free A fragment LDS
    constexpr int BPAD = BN + 8;    // 136 -> conflict-free B fragment LDS
    constexpr int NBUF = (PASSES == 3) ? 2 : 1;
    __shared__ float As[NBUF][BM * APAD];
    __shared__ float Bs[NBUF][BK * BPAD];

    const int z = blockIdx.z;
    const float* A = Ag + (long long)z * sA;
    const float* B = Bg + (long long)z * sB;
    float* C = Cg + (long long)z * sC;

    const int rowBase = blockIdx.y * BM;
    const int colBase = blockIdx.x * BN;
    const int tid = threadIdx.x;
    const int lane = tid & 31, warp = tid >> 5;
    const int wm = warp >> 1, wn = warp & 1;  // 4 x 2 warp grid
    const int lrow = lane >> 2, lcol = lane & 3;

    const bool fullTile = (rowBase + BM <= M) && (colBase + BN <= N);

    float acc[2][8][4];
    #pragma unroll
    for (int i = 0; i < 2; i++)
        #pragma unroll
        for (int j = 0; j < 8; j++)
            #pragma unroll
            for (int e = 0; e < 4; e++) acc[i][j][e] = 0.0f;

    const int am = tid >> 2, ak = (tid & 3) * 4;   // A stage
    const int bk = tid >> 4, bn = (tid & 15) * 4;  // B stage (K-major)
    const int tn = tid >> 2, tk = (tid & 3) * 4;   // B stage (transposed)

    float4 stA[2], stB[2];
    const float4 zero4 = make_float4(0.f, 0.f, 0.f, 0.f);

    auto ldA = [&](int kt) {
        #pragma unroll
        for (int h = 0; h < 2; h++) {
            int gm = rowBase + am + h * 64;
            stA[h] = (gm < M) ? *reinterpret_cast<const float4*>(A + (long long)gm * K + kt + ak)
                              : zero4;
        }
    };
    auto ldB = [&](int kt) {
        if (!TRB) {
            #pragma unroll
            for (int h = 0; h < 2; h++) {
                int gn = colBase + bn + h * 64;
                stB[h] = (gn < N) ? *reinterpret_cast<const float4*>(B + (long long)(kt + bk) * N + gn)
                                  : zero4;
            }
        } else {
            #pragma unroll
            for (int h = 0; h < 2; h++) {
                int gn = colBase + tn + h * 64;
                stB[h] = (gn < N) ? *reinterpret_cast<const float4*>(B + (long long)gn * K + kt + tk)
                                  : zero4;
            }
        }
    };
    auto stage = [&]() {
        #pragma unroll
        for (int h = 0; h < 2; h++) {
            int base = (am + h * 64) * APAD + ak;
            if constexpr (PASSES == 3) {
                float4 v = stA[h];
                float4 hi = make_float4(__uint_as_float(tf32u(v.x)), __uint_as_float(tf32u(v.y)),
                                        __uint_as_float(tf32u(v.z)), __uint_as_float(tf32u(v.w)));
                *reinterpret_cast<float4*>(&As[0][base]) = hi;
                *reinterpret_cast<float4*>(&As[1][base]) =
                    make_float4(v.x - hi.x, v.y - hi.y, v.z - hi.z, v.w - hi.w);
            } else {
                *reinterpret_cast<float4*>(&As[0][base]) = stA[h];
            }
        }
        if (!TRB) {
            #pragma unroll
            for (int h = 0; h < 2; h++) {
                int base = bk * BPAD + bn + h * 64;
                if constexpr (PASSES == 3) {
                    float4 v = stB[h];
                    float4 hi = make_float4(__uint_as_float(tf32u(v.x)), __uint_as_float(tf32u(v.y)),
                                            __uint_as_float(tf32u(v.z)), __uint_as_float(tf32u(v.w)));
                    *reinterpret_cast<float4*>(&Bs[0][base]) = hi;
                    *reinterpret_cast<float4*>(&Bs[1][base]) =
                        make_float4(v.x - hi.x, v.y - hi.y, v.z - hi.z, v.w - hi.w);
                } else {
                    *reinterpret_cast<float4*>(&Bs[0][base]) = stB[h];
                }
            }
        } else {
            #pragma unroll
            for (int h = 0; h < 2; h++) {
                int col = tn + h * 64;
                float v[4] = {stB[h].x, stB[h].y, stB[h].z, stB[h].w};
                #pragma unroll
                for (int j = 0; j < 4; j++) {
                    if constexpr (PASSES == 3) {
                        float hi = __uint_as_float(tf32u(v[j]));
                        Bs[0][(tk + j) * BPAD + col] = hi;
                        Bs[1][(tk + j) * BPAD + col] = v[j] - hi;
                    } else {
                        Bs[0][(tk + j) * BPAD + col] = v[j];
                    }
                }
            }
        }
    };

    ldA(0); ldB(0);
    for (int kt = 0; kt < K; kt += BK) {
        __syncthreads();
        stage();
        __syncthreads();
        if (kt + BK < K) { ldA(kt + BK); ldB(kt + BK); }
        #pragma unroll
        for (int ks = 0; ks < 2; ks++) {
            const int k0 = ks * 8;
            unsigned ah[2][4], al[2][4];
            #pragma unroll
            for (int mt = 0; mt < 2; mt++) {
                int mb = (wm * 32 + mt * 16 + lrow) * APAD + k0 + lcol;
                ah[mt][0] = __float_as_uint(As[0][mb]);
                ah[mt][1] = __float_as_uint(As[0][mb + 8 * APAD]);
                ah[mt][2] = __float_as_uint(As[0][mb + 4]);
                ah[mt][3] = __float_as_uint(As[0][mb + 8 * APAD + 4]);
                if constexpr (PASSES == 3) {
                    al[mt][0] = __float_as_uint(As[1][mb]);
                    al[mt][1] = __float_as_uint(As[1][mb + 8 * APAD]);
                    al[mt][2] = __float_as_uint(As[1][mb + 4]);
                    al[mt][3] = __float_as_uint(As[1][mb + 8 * APAD + 4]);
                }
            }
            #pragma unroll
            for (int nt = 0; nt < 8; nt++) {
                int nb = (k0 + lcol) * BPAD + wn * 64 + nt * 8 + lrow;
                unsigned bh0 = __float_as_uint(Bs[0][nb]);
                unsigned bh1 = __float_as_uint(Bs[0][nb + 4 * BPAD]);
                #pragma unroll
                for (int mt = 0; mt < 2; mt++) mma8(acc[mt][nt], ah[mt], bh0, bh1);
                if constexpr (PASSES == 3) {
                    unsigned bl0 = __float_as_uint(Bs[1][nb]);
                    unsigned bl1 = __float_as_uint(Bs[1][nb + 4 * BPAD]);
                    #pragma unroll
                    for (int mt = 0; mt < 2; mt++) {
                        mma8(acc[mt][nt], al[mt], bh0, bh1);
                        mma8(acc[mt][nt], ah[mt], bl0, bl1);
                    }
                }
            }
        }
    }

    float tau = (EPI == 3) ? bias[z] : 0.0f;
    #pragma unroll
    for (int mt = 0; mt < 2; mt++) {
        int gm0 = rowBase + wm * 32 + mt * 16 + lrow;
        int gm1 = gm0 + 8;
        float rd0 = 1.0f, rd1 = 1.0f;
        if (EPI == 4) {
            if (fullTile || gm0 < M) rd0 = 1.0f / aux[(long long)z * M + gm0];
            if (fullTile || gm1 < M) rd1 = 1.0f / aux[(long long)z * M + gm1];
        }
        #pragma unroll
        for (int nt = 0; nt < 8; nt++) {
            int gc = colBase + wn * 64 + nt * 8 + lcol * 2;
            #pragma unroll
            for (int e = 0; e < 4; e++) {
                int gm = (e < 2) ? gm0 : gm1;
                int gn = gc + (e & 1);
                if (!fullTile && (gm >= M || gn >= N)) continue;
                float v = acc[mt][nt][e];
                if (EPI == 1) v += bias[gn];
                else if (EPI == 2) v = fmaxf(v + bias[gn], 0.0f);
                else if (EPI == 3) {
                    float x = (v + 1.0f) * 0.5f;
                    float d = 1.0f - x;
                    v = fmaxf(1.0f - tau * d * d, 0.0f);
                } else if (EPI == 4) v *= (e < 2) ? rd0 : rd1;
                C[(long long)gm * N + gn] = v;
            }
        }
    }
}

static float* sym(const void* s) {
    void* p = nullptr;
    cudaGetSymbolAddress(&p, s);
    return (float*)p;
}

}  // namespace

extern "C" void kernel_launch(void* const* d_in, const int* in_sizes, int n_in,
                              void* d_out, int out_size) {
    const float* q_in  = (const float*)d_in[0];
    const float* k_in  = (const float*)d_in[1];
    const float* v_in  = (const float*)d_in[2];
    const float* astro = (const float*)d_in[3];
    const float* Wq = (const float*)d_in[4];
    const float* bq = (const float*)d_in[5];
    const float* Wk = (const float*)d_in[6];
    const float* bk = (const float*)d_in[7];
    const float* Wv = (const float*)d_in[8];
    const float* bv = (const float*)d_in[9];
    const float* Wo = (const float*)d_in[10];
    const float* bo = (const float*)d_in[11];
    const float* role_matrix = (const float*)d_in[12];
    const float* Wr1 = (const float*)d_in[13];
    const float* br1 = (const float*)d_in[14];
    const float* Wr2 = (const float*)d_in[15];
    const float* astro_scale = (const float*)d_in[16];
    float* out = (float*)d_out;

    float* CRI    = sym(g_CRI);
    float* IMAT   = sym(g_IMAT);
    float* RoleN  = sym(g_RoleN);
    float* RNspec = sym(g_RNspec);
    float* Q      = sym(g_Q);
    float* Kp     = sym(g_K);
    float* Vp     = sym(g_V);
    float* KB     = sym(g_KB);
    float* H1     = sym(g_H1);
    float* Wt     = sym(g_Wt);
    float* Fr     = sym(g_Fr);
    float* Ka     = sym(g_Ka);
    float* P      = sym(g_P);
    float* S      = sym(g_S);
    float* CTX    = sym(g_CTX);
    float* qnorm  = sym(g_qnorm);
    float* rs     = sym(g_rs);
    float* tau    = sym(g_tau);

    // 1. DFT matrices
    fill_fwd_dft<<<(D_ * W2P_ + 255) / 256, 256>>>();
    fill_inv_dft<<<(W2P_ * D_ + 255) / 256, 256>>>();

    // 2. role rows normalize + spectra
    rownorm_kernel<<<R_, 256>>>(role_matrix, RoleN, nullptr, D_);
    mma_gemm<0, false, 1><<<dim3(9, 1, 1), 256>>>(
        RoleN, CRI, RNspec, R_, W2P_, D_, 0, 0, 0, nullptr, nullptr);

    // 3. Q, K, V projections (V is on the value path -> tf32x3)
    mma_gemm<1, false, 1><<<dim3(8, 64, 1), 256>>>(q_in, Wq, Q,  M_, D_, D_, 0, 0, 0, bq, nullptr);
    mma_gemm<1, false, 1><<<dim3(8, 64, 1), 256>>>(k_in, Wk, Kp, M_, D_, D_, 0, 0, 0, bk, nullptr);
    mma_gemm<1, false, 3><<<dim3(8, 64, 1), 256>>>(v_in, Wv, Vp, M_, D_, D_, 0, 0, 0, bv, nullptr);

    // 4. surprise + astro state
    rownorm_kernel<<<M_, 256>>>(Q, Q, qnorm, D_);
    astro_kernel<<<B_, 256>>>(qnorm, astro, astro_scale, out + (out_size - B_));

    // 5. role MLP -> softmax weights
    mma_gemm<2, false, 1><<<dim3(4, 64, 1), 256>>>(Kp, Wr1, H1, M_, H_, D_, 0, 0, 0, br1, nullptr);
    mma_gemm<0, false, 1><<<dim3(1, 64, 1), 256>>>(H1, Wr2, Wt, M_, R_, H_, 0, 0, 0, nullptr, nullptr);
    softmax64<<<M_ / 8, 256>>>(Wt);

    // 6. holographic binding in frequency domain
    mma_gemm<0, false, 1><<<dim3(9, 64, 1), 256>>>(
        Wt, RNspec, Fr, M_, W2P_, R_, 0, 0, 0, nullptr, nullptr);
    mma_gemm<0, false, 1><<<dim3(9, 64, 1), 256>>>(
        Kp, CRI, Ka, M_, W2P_, D_, 0, 0, 0, nullptr, nullptr);
    cmul_kernel<<<(int)(((long long)M_ * NF_ + 255) / 256), 256>>>();
    mma_gemm<0, false, 1><<<dim3(8, 64, 1), 256>>>(
        P, IMAT, KB, M_, D_, W2P_, 0, 0, 0, nullptr, nullptr);

    // 7. normalize K_bound
    rownorm_kernel<<<M_, 256>>>(KB, KB, nullptr, D_);

    // 8. Epanechnikov scores on cosine sim
    mma_gemm<3, true, 1><<<dim3(16, 16, B_), 256>>>(
        Q, KB, S, TQ_, TK_, D_,
        (long long)TQ_ * D_, (long long)TK_ * D_, (long long)TQ_ * TK_, tau, nullptr);

    // 9. denominators, then context = (S @ V) / rowsum   (value path -> tf32x3)
    rowsum_kernel<<<M_, 256>>>(S, rs);
    mma_gemm<4, false, 3><<<dim3(8, 16, B_), 256>>>(
        S, Vp, CTX, TQ_, D_, TK_,
        (long long)TQ_ * TK_, (long long)TK_ * D_, (long long)TQ_ * D_, nullptr, rs);

    // 10. output projection (value path -> tf32x3)
    mma_gemm<1, false, 3><<<dim3(8, 64, 1), 256>>>(CTX, Wo, out, M_, D_, D_, 0, 0, 0, bo, nullptr);
}